// round 7
// baseline (speedup 1.0000x reference)
#include <cuda_runtime.h>

#define N_NODES 100000
#define D_FEAT  128
#define NEG_SLOPE 0.1f

// scratch (allocation-free rule: __device__ globals)
__device__ float g_node_sum[N_NODES];
__device__ float g_r1[N_NODES];

// Kernel A: one warp per node row-sum; lane l loads float4 #l of the 128-float row.
// Coalesced 512B per warp. Also zero-initializes r1 (same index space).
__global__ void node_sum_kernel(const float* __restrict__ feat) {
    int gtid = blockIdx.x * blockDim.x + threadIdx.x;
    int node = gtid >> 5;
    int lane = gtid & 31;
    if (node >= N_NODES) return;
    const float4* row = reinterpret_cast<const float4*>(feat + (size_t)node * D_FEAT);
    float4 v = row[lane];
    float s = (v.x + v.y) + (v.z + v.w);
    #pragma unroll
    for (int o = 16; o > 0; o >>= 1)
        s += __shfl_xor_sync(0xFFFFFFFFu, s, o);
    if (lane == 0) {
        g_node_sum[node] = s;
        g_r1[node] = 0.0f;
    }
}

// Kernel B: per-edge scatter-add of precomputed node sums (indices are int32).
// Vectorized: each thread handles 4 edges via int4 loads (16B coalesced).
// Edge lists stream from DRAM; node_sum/r1 (400KB each) stay L2-resident.
__global__ void edge_scatter_kernel(const int* __restrict__ src,
                                    const int* __restrict__ dst,
                                    int n_edges4) {
    int i = blockIdx.x * blockDim.x + threadIdx.x;
    int stride = gridDim.x * blockDim.x;
    const int4* src4 = reinterpret_cast<const int4*>(src);
    const int4* dst4 = reinterpret_cast<const int4*>(dst);
    for (; i < n_edges4; i += stride) {
        int4 s = src4[i];
        int4 d = dst4[i];
        atomicAdd(&g_r1[d.x], g_node_sum[s.x]);
        atomicAdd(&g_r1[d.y], g_node_sum[s.y]);
        atomicAdd(&g_r1[d.z], g_node_sum[s.z]);
        atomicAdd(&g_r1[d.w], g_node_sum[s.w]);
    }
}

// Tail kernel for n_edges not divisible by 4 (launched only if needed).
__global__ void edge_scatter_tail_kernel(const int* __restrict__ src,
                                         const int* __restrict__ dst,
                                         int start, int n_edges) {
    int i = start + blockIdx.x * blockDim.x + threadIdx.x;
    if (i < n_edges)
        atomicAdd(&g_r1[dst[i]], g_node_sum[src[i]]);
}

// Kernel C: leaky-relu chain + truncate-toward-zero (matching astype(int32)),
// written as FLOAT32 — the harness compares in the __output__ float32 dtype.
__global__ void epilogue_kernel(float* __restrict__ out) {
    int i = blockIdx.x * blockDim.x + threadIdx.x;
    if (i >= N_NODES) return;
    float r1 = g_r1[i];
    float a1 = (r1 >= 0.0f) ? r1 : NEG_SLOPE * r1;
    float r2 = 16.0f * a1;                       // HIDDEN = 16
    float a2 = (r2 >= 0.0f) ? r2 : NEG_SLOPE * r2;
    float r3 = 10.0f * a2;                       // N_CLASSES = 10
    out[i] = truncf(r3);                         // int-valued float (astype int32 semantics)
}

extern "C" void kernel_launch(void* const* d_in, const int* in_sizes, int n_in,
                              void* d_out, int out_size) {
    const float* feat = (const float*)d_in[0];
    const int*   esrc = (const int*)d_in[1];
    const int*   edst = (const int*)d_in[2];
    int n_edges = in_sizes[1];
    float* out = (float*)d_out;

    // Kernel A: 32 threads per node
    {
        int threads = 256;
        int warps_per_block = threads / 32;
        int blocks = (N_NODES + warps_per_block - 1) / warps_per_block;
        node_sum_kernel<<<blocks, threads>>>(feat);
    }
    // Kernel B: 4 edges per thread
    {
        int n4 = n_edges / 4;
        int threads = 256;
        int blocks = (n4 + threads - 1) / threads;
        if (blocks > 0)
            edge_scatter_kernel<<<blocks, threads>>>(esrc, edst, n4);
        int tail_start = n4 * 4;
        int tail = n_edges - tail_start;
        if (tail > 0)
            edge_scatter_tail_kernel<<<1, 256>>>(esrc, edst, tail_start, n_edges);
    }
    // Kernel C
    {
        int threads = 256;
        int blocks = (N_NODES + threads - 1) / threads;
        epilogue_kernel<<<blocks, threads>>>(out);
    }
}

// round 8
// speedup vs baseline: 1.0117x; 1.0117x over previous
#include <cuda_runtime.h>

#define N_NODES 100000
#define D_FEAT  128
#define NEG_SLOPE 0.1f

// scratch (allocation-free rule: __device__ globals)
__device__ float g_node_sum[N_NODES];
__device__ float g_r1[N_NODES];

// Kernel A: one warp per 4 nodes. Lane l loads float4 #l of each of the 4 rows
// (4 independent LDG.128 = MLP 4) before reducing. Also zero-initializes r1.
__global__ void node_sum_kernel(const float* __restrict__ feat) {
    int gtid = blockIdx.x * blockDim.x + threadIdx.x;
    int warp = gtid >> 5;
    int lane = gtid & 31;
    int node0 = warp * 4;
    if (node0 >= N_NODES) return;

    const float4* f4 = reinterpret_cast<const float4*>(feat);
    // 4 independent loads issued back-to-back (front-batched MLP=4)
    int nvalid = N_NODES - node0;  // >=1 here; full groups are the common case
    float4 v0, v1, v2, v3;
    v0 = f4[(size_t)(node0 + 0) * 32 + lane];
    v1 = (nvalid > 1) ? f4[(size_t)(node0 + 1) * 32 + lane] : make_float4(0, 0, 0, 0);
    v2 = (nvalid > 2) ? f4[(size_t)(node0 + 2) * 32 + lane] : make_float4(0, 0, 0, 0);
    v3 = (nvalid > 3) ? f4[(size_t)(node0 + 3) * 32 + lane] : make_float4(0, 0, 0, 0);

    float s0 = (v0.x + v0.y) + (v0.z + v0.w);
    float s1 = (v1.x + v1.y) + (v1.z + v1.w);
    float s2 = (v2.x + v2.y) + (v2.z + v2.w);
    float s3 = (v3.x + v3.y) + (v3.z + v3.w);
    #pragma unroll
    for (int o = 16; o > 0; o >>= 1) {
        s0 += __shfl_xor_sync(0xFFFFFFFFu, s0, o);
        s1 += __shfl_xor_sync(0xFFFFFFFFu, s1, o);
        s2 += __shfl_xor_sync(0xFFFFFFFFu, s2, o);
        s3 += __shfl_xor_sync(0xFFFFFFFFu, s3, o);
    }
    if (lane == 0) {
        g_node_sum[node0] = s0;  g_r1[node0] = 0.0f;
        if (nvalid > 1) { g_node_sum[node0 + 1] = s1;  g_r1[node0 + 1] = 0.0f; }
        if (nvalid > 2) { g_node_sum[node0 + 2] = s2;  g_r1[node0 + 2] = 0.0f; }
        if (nvalid > 3) { g_node_sum[node0 + 3] = s3;  g_r1[node0 + 3] = 0.0f; }
    }
}

// Kernel B: per-edge scatter-add of precomputed node sums (indices are int32).
// 8 edges/thread: two int4 loads per index array, 8 independent random gathers
// in flight to hide L2 latency, then 8 REDG atomics.
// Edge lists stream from DRAM; node_sum/r1 (400KB each) stay L2-resident.
__global__ void edge_scatter_kernel(const int* __restrict__ src,
                                    const int* __restrict__ dst,
                                    int n_groups8) {
    int i = blockIdx.x * blockDim.x + threadIdx.x;
    int stride = gridDim.x * blockDim.x;
    const int4* src4 = reinterpret_cast<const int4*>(src);
    const int4* dst4 = reinterpret_cast<const int4*>(dst);
    for (; i < n_groups8; i += stride) {
        int4 sa = src4[2 * i];
        int4 sb = src4[2 * i + 1];
        int4 da = dst4[2 * i];
        int4 db = dst4[2 * i + 1];
        // front-batch the 8 random gathers (independent loads)
        float m0 = g_node_sum[sa.x];
        float m1 = g_node_sum[sa.y];
        float m2 = g_node_sum[sa.z];
        float m3 = g_node_sum[sa.w];
        float m4 = g_node_sum[sb.x];
        float m5 = g_node_sum[sb.y];
        float m6 = g_node_sum[sb.z];
        float m7 = g_node_sum[sb.w];
        atomicAdd(&g_r1[da.x], m0);
        atomicAdd(&g_r1[da.y], m1);
        atomicAdd(&g_r1[da.z], m2);
        atomicAdd(&g_r1[da.w], m3);
        atomicAdd(&g_r1[db.x], m4);
        atomicAdd(&g_r1[db.y], m5);
        atomicAdd(&g_r1[db.z], m6);
        atomicAdd(&g_r1[db.w], m7);
    }
}

// Tail kernel for n_edges not divisible by 8 (launched only if needed).
__global__ void edge_scatter_tail_kernel(const int* __restrict__ src,
                                         const int* __restrict__ dst,
                                         int start, int n_edges) {
    int i = start + blockIdx.x * blockDim.x + threadIdx.x;
    if (i < n_edges)
        atomicAdd(&g_r1[dst[i]], g_node_sum[src[i]]);
}

// Kernel C: leaky-relu chain + truncate-toward-zero (astype(int32) semantics),
// written as float32 (harness __output__ dtype).
__global__ void epilogue_kernel(float* __restrict__ out) {
    int i = blockIdx.x * blockDim.x + threadIdx.x;
    if (i >= N_NODES) return;
    float r1 = g_r1[i];
    float a1 = (r1 >= 0.0f) ? r1 : NEG_SLOPE * r1;
    float r2 = 16.0f * a1;                       // HIDDEN = 16
    float a2 = (r2 >= 0.0f) ? r2 : NEG_SLOPE * r2;
    float r3 = 10.0f * a2;                       // N_CLASSES = 10
    out[i] = truncf(r3);
}

extern "C" void kernel_launch(void* const* d_in, const int* in_sizes, int n_in,
                              void* d_out, int out_size) {
    const float* feat = (const float*)d_in[0];
    const int*   esrc = (const int*)d_in[1];
    const int*   edst = (const int*)d_in[2];
    int n_edges = in_sizes[1];
    float* out = (float*)d_out;

    // Kernel A: warp per 4 nodes
    {
        int threads = 256;                       // 8 warps = 32 nodes per block
        int nodes_per_block = (threads / 32) * 4;
        int blocks = (N_NODES + nodes_per_block - 1) / nodes_per_block;
        node_sum_kernel<<<blocks, threads>>>(feat);
    }
    // Kernel B: 8 edges per thread
    {
        int n8 = n_edges / 8;
        int threads = 256;
        int blocks = (n8 + threads - 1) / threads;
        if (blocks > 0)
            edge_scatter_kernel<<<blocks, threads>>>(esrc, edst, n8);
        int tail_start = n8 * 8;
        int tail = n_edges - tail_start;
        if (tail > 0)
            edge_scatter_tail_kernel<<<1, 256>>>(esrc, edst, tail_start, n_edges);
    }
    // Kernel C
    {
        int threads = 256;
        int blocks = (N_NODES + threads - 1) / threads;
        epilogue_kernel<<<blocks, threads>>>(out);
    }
}

// round 9
// speedup vs baseline: 1.0511x; 1.0390x over previous
#include <cuda_runtime.h>

#define N_NODES 100000
#define D_FEAT  128
#define NEG_SLOPE 0.1f

// scratch (allocation-free rule: __device__ globals)
__device__ float g_node_sum[N_NODES];
__device__ float g_r1[N_NODES];

// Kernel A: one warp per 8 nodes. Lane l loads float4 #l of each of the 8 rows
// (8 independent LDG.128 = MLP 8) before reducing. 100000 = 8*12500, so every
// warp with node0 < N_NODES has a full group of 8 — no per-node predication.
// Also zero-initializes r1.
__global__ void node_sum_kernel(const float* __restrict__ feat) {
    int gtid = blockIdx.x * blockDim.x + threadIdx.x;
    int warp = gtid >> 5;
    int lane = gtid & 31;
    int node0 = warp * 8;
    if (node0 >= N_NODES) return;

    const float4* f4 = reinterpret_cast<const float4*>(feat);
    float4 v[8];
    #pragma unroll
    for (int k = 0; k < 8; k++)
        v[k] = f4[(size_t)(node0 + k) * 32 + lane];

    float s[8];
    #pragma unroll
    for (int k = 0; k < 8; k++)
        s[k] = (v[k].x + v[k].y) + (v[k].z + v[k].w);

    #pragma unroll
    for (int o = 16; o > 0; o >>= 1) {
        #pragma unroll
        for (int k = 0; k < 8; k++)
            s[k] += __shfl_xor_sync(0xFFFFFFFFu, s[k], o);
    }
    if (lane == 0) {
        #pragma unroll
        for (int k = 0; k < 8; k++) {
            g_node_sum[node0 + k] = s[k];
            g_r1[node0 + k] = 0.0f;
        }
    }
}

// Kernel B: per-edge scatter-add of precomputed node sums (indices are int32).
// 4 edges/thread via int4 loads — measured faster than 8/thread (deeper
// front-batching regressed via L1tex queue contention).
// Edge lists stream from DRAM; node_sum/r1 (400KB each) stay L2-resident.
__global__ void edge_scatter_kernel(const int* __restrict__ src,
                                    const int* __restrict__ dst,
                                    int n_edges4) {
    int i = blockIdx.x * blockDim.x + threadIdx.x;
    int stride = gridDim.x * blockDim.x;
    const int4* src4 = reinterpret_cast<const int4*>(src);
    const int4* dst4 = reinterpret_cast<const int4*>(dst);
    for (; i < n_edges4; i += stride) {
        int4 s = src4[i];
        int4 d = dst4[i];
        atomicAdd(&g_r1[d.x], g_node_sum[s.x]);
        atomicAdd(&g_r1[d.y], g_node_sum[s.y]);
        atomicAdd(&g_r1[d.z], g_node_sum[s.z]);
        atomicAdd(&g_r1[d.w], g_node_sum[s.w]);
    }
}

// Tail kernel for n_edges not divisible by 4 (launched only if needed).
__global__ void edge_scatter_tail_kernel(const int* __restrict__ src,
                                         const int* __restrict__ dst,
                                         int start, int n_edges) {
    int i = start + blockIdx.x * blockDim.x + threadIdx.x;
    if (i < n_edges)
        atomicAdd(&g_r1[dst[i]], g_node_sum[src[i]]);
}

// Kernel C: leaky-relu chain + truncate-toward-zero (astype(int32) semantics),
// written as float32 (harness __output__ dtype).
__global__ void epilogue_kernel(float* __restrict__ out) {
    int i = blockIdx.x * blockDim.x + threadIdx.x;
    if (i >= N_NODES) return;
    float r1 = g_r1[i];
    float a1 = (r1 >= 0.0f) ? r1 : NEG_SLOPE * r1;
    float r2 = 16.0f * a1;                       // HIDDEN = 16
    float a2 = (r2 >= 0.0f) ? r2 : NEG_SLOPE * r2;
    float r3 = 10.0f * a2;                       // N_CLASSES = 10
    out[i] = truncf(r3);
}

extern "C" void kernel_launch(void* const* d_in, const int* in_sizes, int n_in,
                              void* d_out, int out_size) {
    const float* feat = (const float*)d_in[0];
    const int*   esrc = (const int*)d_in[1];
    const int*   edst = (const int*)d_in[2];
    int n_edges = in_sizes[1];
    float* out = (float*)d_out;

    // Kernel A: warp per 8 nodes
    {
        int threads = 256;                       // 8 warps = 64 nodes per block
        int nodes_per_block = (threads / 32) * 8;
        int blocks = (N_NODES + nodes_per_block - 1) / nodes_per_block;
        node_sum_kernel<<<blocks, threads>>>(feat);
    }
    // Kernel B: 4 edges per thread
    {
        int n4 = n_edges / 4;
        int threads = 256;
        int blocks = (n4 + threads - 1) / threads;
        if (blocks > 0)
            edge_scatter_kernel<<<blocks, threads>>>(esrc, edst, n4);
        int tail_start = n4 * 4;
        int tail = n_edges - tail_start;
        if (tail > 0)
            edge_scatter_tail_kernel<<<1, 256>>>(esrc, edst, tail_start, n_edges);
    }
    // Kernel C
    {
        int threads = 256;
        int blocks = (N_NODES + threads - 1) / threads;
        epilogue_kernel<<<blocks, threads>>>(out);
    }
}